// round 1
// baseline (speedup 1.0000x reference)
#include <cuda_runtime.h>
#include <cstdint>

// Radon transform: out[b, n, t] = sum_h bilinear(img_b, R(theta_n) * grid(t, h))
// B=2, N=180, H=W=512. Image padded with zero halo so corner loads are unconditional.

#define IMG 512
#define NANG 180
#define NBATCH 2
#define PITCH 516            // padded row pitch (cols -1 .. 513 used -> indices 0..514)
#define PAD_ELEMS (PITCH * PITCH)

__device__ float d_pad[NBATCH * PAD_ELEMS];

// Prologue: zero-fill halo + copy image into padded buffer.
__global__ void pad_kernel(const float* __restrict__ x) {
    int idx = blockIdx.x * blockDim.x + threadIdx.x;
    int total = NBATCH * PAD_ELEMS;
    if (idx >= total) return;
    int b   = idx / PAD_ELEMS;
    int rem = idx - b * PAD_ELEMS;
    int row = rem / PITCH;
    int col = rem - row * PITCH;
    float v = 0.0f;
    // image lives at rows/cols [1, 512] of the padded buffer
    if (row >= 1 && row <= IMG && col >= 1 && col <= IMG) {
        v = x[b * (IMG * IMG) + (row - 1) * IMG + (col - 1)];
    }
    d_pad[idx] = v;
}

__global__ void __launch_bounds__(128) radon_kernel(const float* __restrict__ angles,
                                                    float* __restrict__ out) {
    const int t = blockIdx.x * blockDim.x + threadIdx.x;  // detector column 0..511
    const int n = blockIdx.y;                              // angle
    const int b = blockIdx.z;                              // batch

    const float ang = angles[n] * 0.017453292519943295f;   // deg2rad
    float c, s;
    __sincosf(ang, &s, &c);
    // __sincosf is low precision; use accurate version instead:
    s = sinf(ang);
    c = cosf(ang);

    const float half = 0.5f * (float)(IMG - 1);            // 255.5
    const float X = -1.0f + (float)t * (2.0f / (float)(IMG - 1));

    // ix(h) = half*(c*X - s*Y_h + 1), Y_h = -1 + h * 2/(H-1)
    //       = ix0 - h*s      (since W==H)
    // iy(h) = half*(s*X + c*Y_h + 1) = iy0 + h*c
    const float ix0 = half * (c * X + s + 1.0f);
    const float iy0 = half * (s * X - c + 1.0f);
    const float dix = -s;
    const float diy = c;

    const float* __restrict__ img = d_pad + b * PAD_ELEMS;

    float acc = 0.0f;
#pragma unroll 4
    for (int h = 0; h < IMG; ++h) {
        const float hf = (float)h;
        float ix = fmaf(hf, dix, ix0);
        float iy = fmaf(hf, diy, iy0);
        // clamp so padded (2-wide high side, 1-wide low side) halo absorbs OOB:
        // ix in [-1, 512] -> x0 in [-1, 512], x0+1 in [0, 513]; weights give exact zeros.
        ix = fminf(fmaxf(ix, -1.0f), 512.0f);
        iy = fminf(fmaxf(iy, -1.0f), 512.0f);

        const int xi = __float2int_rd(ix);
        const int yi = __float2int_rd(iy);
        const float fx = ix - __int2float_rn(xi);
        const float fy = iy - __int2float_rn(yi);

        const float* p = img + (yi + 1) * PITCH + (xi + 1);
        const float v00 = __ldg(p);
        const float v10 = __ldg(p + 1);
        const float v01 = __ldg(p + PITCH);
        const float v11 = __ldg(p + PITCH + 1);

        const float top = fmaf(fx, v10 - v00, v00);
        const float bot = fmaf(fx, v11 - v01, v01);
        acc = fmaf(fy, bot - top, acc + top);
    }

    out[(b * NANG + n) * IMG + t] = acc;
}

extern "C" void kernel_launch(void* const* d_in, const int* in_sizes, int n_in,
                              void* d_out, int out_size) {
    const float* x      = (const float*)d_in[0];   // [2,1,512,512]
    const float* angles = (const float*)d_in[1];   // [180]
    float* out          = (float*)d_out;           // [2,180,512]

    {
        int total = NBATCH * PAD_ELEMS;
        int threads = 256;
        int blocks = (total + threads - 1) / threads;
        pad_kernel<<<blocks, threads>>>(x);
    }
    {
        dim3 block(128, 1, 1);
        dim3 grid(IMG / 128, NANG, NBATCH);
        radon_kernel<<<grid, block>>>(angles, out);
    }
}

// round 2
// speedup vs baseline: 1.9231x; 1.9231x over previous
#include <cuda_runtime.h>
#include <cstdint>

// Radon transform: out[b, n, t] = sum_h bilinear(img_b, R(theta_n) * grid(t, h))
// B=2, N=180, H=W=512. Image padded with zero halo so corner loads are unconditional.
//
// Warp layout: 8 detector columns (t) x 4 h-phases per warp, so each warp-load's
// 32 sample points cover a ~10x10 pixel patch at ANY angle (few L1 lines) instead
// of a 32-sample streak spanning up to ~23 rows.

#define IMG 512
#define NANG 180
#define NBATCH 2
#define PITCH 516            // padded row pitch (cols -1 .. 513 used -> indices 0..514)
#define PAD_ELEMS (PITCH * PITCH)

__device__ float d_pad[NBATCH * PAD_ELEMS];

// Prologue: zero-fill halo + copy image into padded buffer.
__global__ void pad_kernel(const float* __restrict__ x) {
    int idx = blockIdx.x * blockDim.x + threadIdx.x;
    int total = NBATCH * PAD_ELEMS;
    if (idx >= total) return;
    int b   = idx / PAD_ELEMS;
    int rem = idx - b * PAD_ELEMS;
    int row = rem / PITCH;
    int col = rem - row * PITCH;
    float v = 0.0f;
    if (row >= 1 && row <= IMG && col >= 1 && col <= IMG) {
        v = x[b * (IMG * IMG) + (row - 1) * IMG + (col - 1)];
    }
    d_pad[idx] = v;
}

__global__ void __launch_bounds__(128) radon_kernel(const float* __restrict__ angles,
                                                    float* __restrict__ out) {
    const int warp = threadIdx.x >> 5;
    const int lane = threadIdx.x & 31;
    const int i = lane & 7;          // t within warp's 8-wide tile
    const int p = lane >> 3;         // h phase 0..3

    const int t = blockIdx.x * 32 + warp * 8 + i;  // detector column
    const int n = blockIdx.y;                      // angle
    const int b = blockIdx.z;                      // batch

    const float ang = angles[n] * 0.017453292519943295f;   // deg2rad
    const float s = sinf(ang);
    const float c = cosf(ang);

    const float half = 0.5f * (float)(IMG - 1);            // 255.5
    const float X = -1.0f + (float)t * (2.0f / (float)(IMG - 1));

    // ix(h) = half*(c*X - s*Y_h + 1) = ix0 - h*s ;  iy(h) = iy0 + h*c
    const float ix0 = half * (c * X + s + 1.0f);
    const float iy0 = half * (s * X - c + 1.0f);
    const float dix = -s;
    const float diy = c;

    const float* __restrict__ img = d_pad + b * PAD_ELEMS;

    float acc = 0.0f;
#pragma unroll 4
    for (int k = 0; k < IMG / 4; ++k) {
        const float hf = (float)(4 * k + p);
        float ix = fmaf(hf, dix, ix0);
        float iy = fmaf(hf, diy, iy0);
        // clamp so the zero halo absorbs OOB; weights give exact zeros there.
        ix = fminf(fmaxf(ix, -1.0f), 512.0f);
        iy = fminf(fmaxf(iy, -1.0f), 512.0f);

        const int xi = __float2int_rd(ix);
        const int yi = __float2int_rd(iy);
        const float fx = ix - __int2float_rn(xi);
        const float fy = iy - __int2float_rn(yi);

        const float* ptr = img + (yi + 1) * PITCH + (xi + 1);
        const float v00 = __ldg(ptr);
        const float v10 = __ldg(ptr + 1);
        const float v01 = __ldg(ptr + PITCH);
        const float v11 = __ldg(ptr + PITCH + 1);

        const float top = fmaf(fx, v10 - v00, v00);
        const float bot = fmaf(fx, v11 - v01, v01);
        acc = fmaf(fy, bot - top, acc + top);
    }

    // Fold the 4 h-phases (lanes p=0..3 share the same t, lane ids differ by 8/16/24).
    acc += __shfl_xor_sync(0xffffffffu, acc, 8);
    acc += __shfl_xor_sync(0xffffffffu, acc, 16);

    if (p == 0) {
        out[(b * NANG + n) * IMG + t] = acc;
    }
}

extern "C" void kernel_launch(void* const* d_in, const int* in_sizes, int n_in,
                              void* d_out, int out_size) {
    const float* x      = (const float*)d_in[0];   // [2,1,512,512]
    const float* angles = (const float*)d_in[1];   // [180]
    float* out          = (float*)d_out;           // [2,180,512]

    {
        int total = NBATCH * PAD_ELEMS;
        int threads = 256;
        int blocks = (total + threads - 1) / threads;
        pad_kernel<<<blocks, threads>>>(x);
    }
    {
        dim3 block(128, 1, 1);
        dim3 grid(IMG / 32, NANG, NBATCH);   // 16 x 180 x 2 = 5760 blocks
        radon_kernel<<<grid, block>>>(angles, out);
    }
}

// round 3
// speedup vs baseline: 1.9287x; 1.0029x over previous
#include <cuda_runtime.h>
#include <cstdint>

// Radon transform: out[b, n, t] = sum_h bilinear(img_b, R(theta_n) * grid(t, h))
// B=2, N=180, H=W=512.
//
// Quad-image trick: precompute Q[y][x] = float4(P(y,x), P(y,x+1), P(y+1,x), P(y+1,x+1))
// over the zero-padded grid, so every bilinear sample is ONE aligned LDG.128 instead
// of four scalar gathers. Warp tile is 8(t) x 4(h) so the 32 samples of any warp-load
// land in a ~10x10 pixel patch (few L1 lines) at every angle.

#define IMG 512
#define NANG 180
#define NBATCH 2
#define QPITCH 516                    // quad row pitch; valid quad cols 0..514
#define QELEMS (QPITCH * QPITCH)

__device__ float4 d_quad[NBATCH * QELEMS];

// Prologue: build quad image. P(r,c) = img[r-1][c-1] if 1<=r,c<=IMG else 0.
__global__ void quad_kernel(const float* __restrict__ x) {
    int idx = blockIdx.x * blockDim.x + threadIdx.x;
    int total = NBATCH * QELEMS;
    if (idx >= total) return;
    int b   = idx / QELEMS;
    int rem = idx - b * QELEMS;
    int r   = rem / QPITCH;
    int cc  = rem - r * QPITCH;

    const float* img = x + b * (IMG * IMG);
    float4 q = make_float4(0.0f, 0.0f, 0.0f, 0.0f);

    int r0 = r - 1, r1 = r;          // unpadded rows for P(r,.), P(r+1,.)
    int c0 = cc - 1, c1 = cc;        // unpadded cols for P(.,c), P(.,c+1)
    bool vr0 = (unsigned)r0 < IMG, vr1 = (unsigned)r1 < IMG;
    bool vc0 = (unsigned)c0 < IMG, vc1 = (unsigned)c1 < IMG;
    if (vr0 && vc0) q.x = img[r0 * IMG + c0];
    if (vr0 && vc1) q.y = img[r0 * IMG + c1];
    if (vr1 && vc0) q.z = img[r1 * IMG + c0];
    if (vr1 && vc1) q.w = img[r1 * IMG + c1];

    d_quad[idx] = q;
}

__global__ void __launch_bounds__(128) radon_kernel(const float* __restrict__ angles,
                                                    float* __restrict__ out) {
    const int warp = threadIdx.x >> 5;
    const int lane = threadIdx.x & 31;
    const int i = lane & 7;          // t within warp's 8-wide tile
    const int p = lane >> 3;         // h phase 0..3

    const int t = blockIdx.x * 32 + warp * 8 + i;  // detector column
    const int n = blockIdx.y;                      // angle
    const int b = blockIdx.z;                      // batch

    const float ang = angles[n] * 0.017453292519943295f;   // deg2rad
    const float s = sinf(ang);
    const float c = cosf(ang);

    const float half = 0.5f * (float)(IMG - 1);            // 255.5
    const float X = -1.0f + (float)t * (2.0f / (float)(IMG - 1));

    // ix(h) = ix0 - h*s ;  iy(h) = iy0 + h*c   (unit rotated-lattice steps)
    const float ix0 = half * (c * X + s + 1.0f);
    const float iy0 = half * (s * X - c + 1.0f);
    const float dix = -s;
    const float diy = c;

    const float4* __restrict__ quad = d_quad + b * QELEMS;

    float acc = 0.0f;
#pragma unroll 4
    for (int k = 0; k < IMG / 4; ++k) {
        const float hf = (float)(4 * k + p);
        float ix = fmaf(hf, dix, ix0);
        float iy = fmaf(hf, diy, iy0);
        // clamp so the zero halo absorbs OOB; weights give exact zeros there.
        ix = fminf(fmaxf(ix, -1.0f), 512.0f);
        iy = fminf(fmaxf(iy, -1.0f), 512.0f);

        const int xi = __float2int_rd(ix);
        const int yi = __float2int_rd(iy);
        const float fx = ix - __int2float_rn(xi);
        const float fy = iy - __int2float_rn(yi);

        const float4 v = __ldg(quad + (yi + 1) * QPITCH + (xi + 1));

        const float top = fmaf(fx, v.y - v.x, v.x);
        const float bot = fmaf(fx, v.w - v.z, v.z);
        acc = fmaf(fy, bot - top, acc + top);
    }

    // Fold the 4 h-phases (lanes p=0..3 share the same t).
    acc += __shfl_xor_sync(0xffffffffu, acc, 8);
    acc += __shfl_xor_sync(0xffffffffu, acc, 16);

    if (p == 0) {
        out[(b * NANG + n) * IMG + t] = acc;
    }
}

extern "C" void kernel_launch(void* const* d_in, const int* in_sizes, int n_in,
                              void* d_out, int out_size) {
    const float* x      = (const float*)d_in[0];   // [2,1,512,512]
    const float* angles = (const float*)d_in[1];   // [180]
    float* out          = (float*)d_out;           // [2,180,512]

    {
        int total = NBATCH * QELEMS;
        int threads = 256;
        int blocks = (total + threads - 1) / threads;
        quad_kernel<<<blocks, threads>>>(x);
    }
    {
        dim3 block(128, 1, 1);
        dim3 grid(IMG / 32, NANG, NBATCH);   // 16 x 180 x 2 = 5760 blocks
        radon_kernel<<<grid, block>>>(angles, out);
    }
}